// round 2
// baseline (speedup 1.0000x reference)
#include <cuda_runtime.h>
#include <cuda_fp16.h>
#include <stdint.h>
#include <string.h>

// Problem constants
#define IN_F   2048
#define OUTF   512
#define NB     8
#define BATCH  16

// Packed bits: g_pkw[fb8][out][sub] : uint32, nibble j (bits 4j..4j+3) holds the
// 4 weight bits for f = fb8*8 + j, lanes L..L+3 where L = sub*4, column out*8+L+k.
// Dims: 256 x 512 x 2 = 262144 words = 1 MB.
__device__ uint32_t g_pkw[256 * 512 * 2];

static __device__ __forceinline__ __half2 u2h2(uint32_t u) {
    __half2 h; memcpy(&h, &u, 4); return h;
}
static __device__ __forceinline__ uint32_t h22u(__half2 h) {
    uint32_t u; memcpy(&u, &h, 4); return u;
}

// ---------------------------------------------------------------------------
// Pack kernel: binarize weight (>= 0.5) and pack into nibble stream.
// One thread per output word. idx = fb8*1024 + (out*2 + sub).
// Reads are fully coalesced (consecutive threads read consecutive float4).
// ---------------------------------------------------------------------------
__global__ void pack_kernel(const float* __restrict__ w) {
    int idx = blockIdx.x * blockDim.x + threadIdx.x;
    int fb8 = idx >> 10;          // f-chunk of 8
    int rem = idx & 1023;         // out*2 + sub  -> column base = rem*4
    const float4* wp = reinterpret_cast<const float4*>(w) + rem;  // + f*1024 per row
    uint32_t word = 0;
#pragma unroll
    for (int j = 0; j < 8; j++) {
        float4 v = __ldg(wp + (size_t)(fb8 * 8 + j) * 1024);
        uint32_t nib = (v.x >= 0.5f ? 1u : 0u) | (v.y >= 0.5f ? 2u : 0u) |
                       (v.z >= 0.5f ? 4u : 0u) | (v.w >= 0.5f ? 8u : 0u);
        word |= nib << (4 * j);
    }
    g_pkw[idx] = word;
}

// ---------------------------------------------------------------------------
// One CSA pair update (2 lanes packed in half2), exact fp16 rounding emulation
// of the JAX reference:
//   xor(u,v) = (u+v) - round(2u*v)      [round(2u*v) == 2*round(u*v), x2 exact]
//   maj(s,a,c) = ((s*a)+(s*c)) + (a*c) - round(2*s*a*c)
// HFMA2(m, -2, p) == round(p - 2m) == round(p - round(2uv)) : bit-identical.
// 12 half2 ops on the fma pipe.
// ---------------------------------------------------------------------------
static __device__ __forceinline__ void csa_pair(__half2 a, __half2& s, __half2 c,
                                                __half2& mj, __half2 neg2) {
    __half2 m1 = __hmul2(s, a);          // round(s*a)
    __half2 p  = __hadd2(s, a);
    __half2 r  = __hfma2(m1, neg2, p);   // xor(s, a)
    __half2 mc = __hmul2(s, c);
    __half2 t1 = __hadd2(m1, mc);
    __half2 m3 = __hmul2(a, c);
    __half2 t2 = __hadd2(t1, m3);
    __half2 q  = __hmul2(m1, c);         // round(m1*c); 2q == round(2 s a c)
    mj = __hfma2(q, neg2, t2);           // maj(s, a, c)
    __half2 p2 = __hadd2(r, c);
    __half2 q2 = __hmul2(r, c);
    s = __hfma2(q2, neg2, p2);           // new s = xor(r, c)
}

// ---------------------------------------------------------------------------
// Scan kernel: 2 threads per row (b,out); thread sub handles lanes 4*sub..4*sub+3
// as two half2 pairs. Carry shift crosses the split via one shfl_up per step.
// Grid: 128 blocks x 128 threads. Block = 64 rows of one batch b.
// Output: float32. s at out[b*4096 + o*8 + nb], c at out[65536 + same].
// ---------------------------------------------------------------------------
__global__ void __launch_bounds__(128, 1)
scan_kernel(const float* __restrict__ x, float* __restrict__ out) {
    __shared__ uint32_t sx[IN_F];   // x row as duplicated half2 (broadcast reads)
    __shared__ uint2 slut[16];      // nibble -> (mask pair0, mask pair1)

    const int tid = threadIdx.x;
    const int blk = blockIdx.x;
    const int b = blk >> 3;                 // 8 blocks per batch row
    const int out_base = (blk & 7) << 6;    // 64 outs per block

    // Load x[b, :] as fp16, duplicated into both halves of a half2.
    const float* xr = x + b * IN_F;
#pragma unroll
    for (int i = 0; i < IN_F / 128; i++) {
        int k = tid + i * 128;
        __half h = __float2half(xr[k]);     // matches jnp astype(float16)
        sx[k] = h22u(__half2half2(h));
    }
    if (tid < 16) {
        uint32_t n = tid;
        uint32_t m0 = ((n & 1u) ? 0x0000FFFFu : 0u) | ((n & 2u) ? 0xFFFF0000u : 0u);
        uint32_t m1 = ((n & 4u) ? 0x0000FFFFu : 0u) | ((n & 8u) ? 0xFFFF0000u : 0u);
        slut[n] = make_uint2(m0, m1);
    }
    __syncthreads();

    const int sub = tid & 1;
    const uint32_t submask = sub ? 0xFFFFFFFFu : 0u;   // zero carry-in at lane 0
    const uint32_t* pk = g_pkw + out_base * 2 + tid;   // + fb8*1024 per chunk
    const __half2 neg2 = __float2half2_rn(-2.0f);

    uint32_t w = __ldg(pk);

    // f = 0 initializes the state: s = a(f=0), c = 0.
    uint2 m_init = slut[w & 0xFu];
    uint32_t xv0 = sx[0];
    __half2 s0 = u2h2(xv0 & m_init.x);
    __half2 s1 = u2h2(xv0 & m_init.y);
    __half2 c0 = __float2half2_rn(0.0f);
    __half2 c1 = __float2half2_rn(0.0f);

    auto step = [&](uint32_t nib, uint32_t xvu) {
        uint2 m = slut[nib];
        __half2 a0 = u2h2(xvu & m.x);
        __half2 a1 = u2h2(xvu & m.y);
        __half2 mj0, mj1;
        csa_pair(a0, s0, c0, mj0, neg2);
        csa_pair(a1, s1, c1, mj1, neg2);
        uint32_t mj0u = h22u(mj0);
        uint32_t mj1u = h22u(mj1);
        // carry shift: c_new[k] = maj[k-1], c_new[0] = 0 (global lane 0)
        uint32_t prev = __shfl_up_sync(0xFFFFFFFFu, mj1u, 1) & submask;
        c0 = u2h2(__funnelshift_r(prev, mj0u, 16));   // {maj[L-1], maj[L]}
        c1 = u2h2(__funnelshift_r(mj0u, mj1u, 16));   // {maj[L+1], maj[L+2]}
    };

    // Peel chunk 0 (f = 1..7), prefetching the next word.
    uint32_t wn = __ldg(pk + 1024);
#pragma unroll
    for (int j = 1; j < 8; j++) step((w >> (4 * j)) & 0xFu, sx[j]);
    w = wn;

#pragma unroll 1
    for (int fb8 = 1; fb8 < 256; fb8++) {
        uint32_t wnext = 0;
        if (fb8 < 255) wnext = __ldg(pk + (fb8 + 1) * 1024);
        const uint32_t* sxp = sx + fb8 * 8;
#pragma unroll
        for (int j = 0; j < 8; j++) step((w >> (4 * j)) & 0xFu, sxp[j]);
        w = wnext;
    }

    // Outputs as float32. s flat index = b*4096 + out*8 + nb; c follows at
    // +65536 floats with the same inner layout. One float4 store each.
    const int out_i = out_base + (tid >> 1);
    const int f4i = b * 1024 + out_i * 2 + sub;    // float4 index (4 lanes)
    float2 s0f = __half22float2(s0);
    float2 s1f = __half22float2(s1);
    float2 c0f = __half22float2(c0);
    float2 c1f = __half22float2(c1);
    float4* o4 = reinterpret_cast<float4*>(out);
    o4[f4i]         = make_float4(s0f.x, s0f.y, s1f.x, s1f.y);
    o4[16384 + f4i] = make_float4(c0f.x, c0f.y, c1f.x, c1f.y);
}

// ---------------------------------------------------------------------------
extern "C" void kernel_launch(void* const* d_in, const int* in_sizes, int n_in,
                              void* d_out, int out_size) {
    const float* x  = (const float*)d_in[0];   // (16, 2048) fp32
    const float* wt = (const float*)d_in[1];   // (2048, 4096) fp32
    float* out = (float*)d_out;                // 131072 fp32: [s | c]

    pack_kernel<<<1024, 256>>>(wt);
    scan_kernel<<<128, 128>>>(x, out);
}

// round 3
// speedup vs baseline: 1.4467x; 1.4467x over previous
#include <cuda_runtime.h>
#include <cuda_fp16.h>
#include <stdint.h>
#include <string.h>

// Problem constants
#define IN_F   2048
#define OUTF   512
#define NB     8
#define BATCH  16

// Packed bits: g_pkw[fb16][out][sub] : uint32. Bit pair (2j, 2j+1) holds the
// weight bits for f = fb16*16 + j, columns out*8 + sub*2 + {0,1}.
// Dims: 128 x 512 x 4 = 262144 words = 1 MB.
__device__ uint32_t g_pkw[128 * 512 * 4];

static __device__ __forceinline__ __half2 u2h2(uint32_t u) {
    __half2 h; memcpy(&h, &u, 4); return h;
}
static __device__ __forceinline__ uint32_t h22u(__half2 h) {
    uint32_t u; memcpy(&u, &h, 4); return u;
}

// ---------------------------------------------------------------------------
// Pack kernel: binarize weight (>= 0.5), 2 bits per (f, thread-pair), 16 f per
// word. idx = fb16*2048 + (out*4 + sub). Consecutive threads read consecutive
// float2 -> fully coalesced.
// ---------------------------------------------------------------------------
__global__ void pack_kernel(const float* __restrict__ w) {
    int idx = blockIdx.x * blockDim.x + threadIdx.x;
    int fb16 = idx >> 11;         // f-chunk of 16
    int rem  = idx & 2047;        // out*4 + sub -> column base = rem*2
    const float2* wp = reinterpret_cast<const float2*>(w) + rem;
    uint32_t word = 0;
#pragma unroll
    for (int j = 0; j < 16; j++) {
        float2 v = __ldg(wp + (size_t)(fb16 * 16 + j) * 2048);
        word |= ((v.x >= 0.5f ? 1u : 0u) | (v.y >= 0.5f ? 2u : 0u)) << (2 * j);
    }
    g_pkw[idx] = word;
}

// ---------------------------------------------------------------------------
// One CSA update on one half2 pair; exact fp16 rounding emulation of the JAX
// reference (see R0 derivation). 12 ops on the fma pipe. Produces new s (in
// place) and mj (pre-shift carry).
// ---------------------------------------------------------------------------
static __device__ __forceinline__ void csa_pair(__half2 a, __half2& s, __half2 c,
                                                __half2& mj, __half2 neg2) {
    __half2 m1 = __hmul2(s, a);          // round(s*a)
    __half2 p  = __hadd2(s, a);
    __half2 r  = __hfma2(m1, neg2, p);   // xor(s, a)
    __half2 mc = __hmul2(s, c);
    __half2 t1 = __hadd2(m1, mc);
    __half2 m3 = __hmul2(a, c);
    __half2 t2 = __hadd2(t1, m3);
    __half2 q  = __hmul2(m1, c);         // 2q == round(2 s a c)
    mj = __hfma2(q, neg2, t2);           // maj(s, a, c)
    __half2 p2 = __hadd2(r, c);
    __half2 q2 = __hmul2(r, c);
    s = __hfma2(q2, neg2, p2);           // new s = xor(r, c)
}

// ---------------------------------------------------------------------------
// Scan kernel: 4 threads per row (b,out); thread sub in {0..3} handles lanes
// {2sub, 2sub+1} as one half2. Carry shift: one shfl_up + funnel shift.
// Grid: 128 blocks x 256 threads (8 warps -> 2 warps/SMSP). Block = 64 rows.
// Output float32: s at out[b*4096 + o*8 + nb], c at +65536 floats.
// ---------------------------------------------------------------------------
__global__ void __launch_bounds__(256, 1)
scan_kernel(const float* __restrict__ x, float* __restrict__ out) {
    __shared__ uint32_t sx[IN_F];   // x row as duplicated half2 (broadcast reads)
    __shared__ uint32_t slut[4];    // 2-bit pattern -> lane mask pair

    const int tid = threadIdx.x;
    const int blk = blockIdx.x;
    const int b = blk >> 3;                 // 8 blocks per batch row
    const int out_base = (blk & 7) << 6;    // 64 outs per block

    const float* xr = x + b * IN_F;
#pragma unroll
    for (int i = 0; i < IN_F / 256; i++) {
        int k = tid + i * 256;
        __half h = __float2half(xr[k]);     // matches jnp astype(float16)
        sx[k] = h22u(__half2half2(h));
    }
    if (tid < 4)
        slut[tid] = ((tid & 1) ? 0x0000FFFFu : 0u) | ((tid & 2) ? 0xFFFF0000u : 0u);
    __syncthreads();

    const int sub = tid & 3;
    const uint32_t submask = sub ? 0xFFFFFFFFu : 0u;   // zero carry-in at lane 0
    const uint32_t* pk = g_pkw + out_base * 4 + tid;   // + fb16*2048 per chunk
    const __half2 neg2 = __float2half2_rn(-2.0f);

    uint32_t w = __ldg(pk);

    // f = 0 initializes the state: s = a(f=0), c = 0.
    __half2 s = u2h2(sx[0] & slut[w & 3u]);
    __half2 c = __float2half2_rn(0.0f);

    auto step = [&](uint32_t two, uint32_t xvu) {
        __half2 a = u2h2(xvu & slut[two]);
        __half2 mj;
        csa_pair(a, s, c, mj, neg2);
        uint32_t mju = h22u(mj);
        // carry shift: c_new[k] = maj[k-1]; lane 0 of the row gets 0.
        uint32_t prev = __shfl_up_sync(0xFFFFFFFFu, mju, 1) & submask;
        c = u2h2(__funnelshift_r(prev, mju, 16));
    };

    // Peel chunk 0 (f = 1..15), prefetching the next word.
    uint32_t wn = __ldg(pk + 2048);
#pragma unroll
    for (int j = 1; j < 16; j++) step((w >> (2 * j)) & 3u, sx[j]);
    w = wn;

#pragma unroll 1
    for (int fb16 = 1; fb16 < 128; fb16++) {
        uint32_t wnext = 0;
        if (fb16 < 127) wnext = __ldg(pk + (fb16 + 1) * 2048);
        const uint32_t* sxp = sx + fb16 * 16;
#pragma unroll
        for (int j = 0; j < 16; j++) step((w >> (2 * j)) & 3u, sxp[j]);
        w = wnext;
    }

    // Output as float32 (one float2 per thread per array).
    const int out_i = out_base + (tid >> 2);
    const int f2i = b * 2048 + out_i * 4 + sub;    // float2 index
    float2* o2 = reinterpret_cast<float2*>(out);
    o2[f2i]         = __half22float2(s);
    o2[32768 + f2i] = __half22float2(c);
}

// ---------------------------------------------------------------------------
extern "C" void kernel_launch(void* const* d_in, const int* in_sizes, int n_in,
                              void* d_out, int out_size) {
    const float* x  = (const float*)d_in[0];   // (16, 2048) fp32
    const float* wt = (const float*)d_in[1];   // (2048, 4096) fp32
    float* out = (float*)d_out;                // 131072 fp32: [s | c]

    pack_kernel<<<1024, 256>>>(wt);
    scan_kernel<<<128, 256>>>(x, out);
}

// round 4
// speedup vs baseline: 1.7906x; 1.2377x over previous
#include <cuda_runtime.h>
#include <cuda_fp16.h>
#include <stdint.h>
#include <string.h>

// Problem constants
#define IN_F   2048
#define OUTF   512
#define NB     8
#define BATCH  16

// Packed bits: g_pkw[fb16][out][sub] : uint32. Bit pair (2j, 2j+1) holds the
// weight bits for f = fb16*16 + j, columns (out*8 + sub) and (out*8 + sub + 4).
// Dims: 128 x 512 x 4 = 262144 words = 1 MB.
__device__ uint32_t g_pkw[128 * 512 * 4];

static __device__ __forceinline__ __half2 u2h2(uint32_t u) {
    __half2 h; memcpy(&h, &u, 4); return h;
}
static __device__ __forceinline__ uint32_t h22u(__half2 h) {
    uint32_t u; memcpy(&u, &h, 4); return u;
}

// ---------------------------------------------------------------------------
// Pack kernel: binarize weight (>= 0.5). Thread (out, sub) packs columns
// out*8+sub (bit 2j) and out*8+sub+4 (bit 2j+1) for 16 consecutive f.
// idx = fb16*2048 + out*4 + sub.
// ---------------------------------------------------------------------------
__global__ void pack_kernel(const float* __restrict__ w) {
    int idx = blockIdx.x * blockDim.x + threadIdx.x;
    int fb16 = idx >> 11;          // f-chunk of 16
    int rem  = idx & 2047;         // out*4 + sub
    int outc = (rem >> 2) * 8 + (rem & 3);
    uint32_t word = 0;
#pragma unroll
    for (int j = 0; j < 16; j++) {
        size_t rowoff = (size_t)(fb16 * 16 + j) * 4096;
        float v0 = __ldg(w + rowoff + outc);
        float v1 = __ldg(w + rowoff + outc + 4);
        word |= ((v0 >= 0.5f ? 1u : 0u) | (v1 >= 0.5f ? 2u : 0u)) << (2 * j);
    }
    g_pkw[idx] = word;
}

// ---------------------------------------------------------------------------
// Scan kernel. 4 threads per row (b,out); thread sub owns lanes {sub, sub+4}
// in one half2. CSA step in 6 fp16 fma-class ops using:
//   r  = xor(s,a)  = fma(a, 1-2s, s)
//   mj = maj(s,a,c)= fma(c, r, s*a)          (exact algebraic identity)
//   s' = xor(r,c)  = fma(c, 1-2r, r)
// Carry shift: previous thread's mj IS the needed pair under this lane map;
// one shfl (wraparound src for sub 0) + one shift (<<16 only for sub 0).
// Grid: 128 blocks x 256 threads (2 warps/SMSP). Block = 64 rows of batch b.
// Output float32: s at out[b*4096 + o*8 + lane], c at +65536 floats.
// ---------------------------------------------------------------------------
__global__ void __launch_bounds__(256, 1)
scan_kernel(const float* __restrict__ x, float* __restrict__ out) {
    __shared__ uint32_t sx[IN_F];   // x row as duplicated half2 (broadcast reads)
    __shared__ uint32_t slut[4];    // 2-bit pattern -> half2 lane mask

    const int tid = threadIdx.x;
    const int blk = blockIdx.x;
    const int b = blk >> 3;                 // 8 blocks per batch row
    const int out_base = (blk & 7) << 6;    // 64 outs per block

    const float* xr = x + b * IN_F;
#pragma unroll
    for (int i = 0; i < IN_F / 256; i++) {
        int k = tid + i * 256;
        __half h = __float2half(xr[k]);     // matches jnp astype(float16)
        sx[k] = h22u(__half2half2(h));
    }
    if (tid < 4)
        slut[tid] = ((tid & 1) ? 0x0000FFFFu : 0u) | ((tid & 2) ? 0xFFFF0000u : 0u);
    __syncthreads();

    const int sub  = tid & 3;
    const int lane = tid & 31;
    const int srcl = (sub == 0) ? lane + 3 : lane - 1;   // carry source lane
    const uint32_t shamt = (sub == 0) ? 16u : 0u;        // zero global lane 0
    const uint32_t* pk = g_pkw + out_base * 4 + tid;     // + fb16*2048 per chunk
    const __half2 neg2 = __float2half2_rn(-2.0f);
    const __half2 one  = __float2half2_rn(1.0f);

    uint32_t w = __ldg(pk);

    // Chunk 0 masks; f = 0 initializes state: s = a(0), c = 0.
    uint32_t av[16];
#pragma unroll
    for (int j = 0; j < 16; j++) av[j] = sx[j] & slut[(w >> (2 * j)) & 3u];
    __half2 s = u2h2(av[0]);
    __half2 c = __float2half2_rn(0.0f);

    auto step = [&](uint32_t au) {
        __half2 a  = u2h2(au);
        __half2 m1 = __hmul2(s, a);
        __half2 g1 = __hfma2(s, neg2, one);
        __half2 r  = __hfma2(a, g1, s);      // xor(s, a)
        __half2 mj = __hfma2(c, r, m1);      // maj(s, a, c)
        __half2 g2 = __hfma2(r, neg2, one);
        s = __hfma2(c, g2, r);               // xor(r, c)
        uint32_t prev = __shfl_sync(0xFFFFFFFFu, h22u(mj), srcl);
        c = u2h2(prev << shamt);
    };

    uint32_t wn = __ldg(pk + 2048);
#pragma unroll
    for (int j = 1; j < 16; j++) step(av[j]);
    w = wn;

#pragma unroll 1
    for (int fb16 = 1; fb16 < 128; fb16++) {
        uint32_t wnext = 0;
        if (fb16 < 127) wnext = __ldg(pk + (fb16 + 1) * 2048);
        const uint32_t* sxp = sx + fb16 * 16;
#pragma unroll
        for (int j = 0; j < 16; j++) av[j] = sxp[j] & slut[(w >> (2 * j)) & 3u];
#pragma unroll
        for (int j = 0; j < 16; j++) step(av[j]);
        w = wnext;
    }

    // Output as float32. Thread sub holds lanes (sub, sub+4).
    const int base = b * 4096 + (out_base + (tid >> 2)) * 8;
    float2 sf = __half22float2(s);
    float2 cf = __half22float2(c);
    out[base + sub]             = sf.x;
    out[base + sub + 4]         = sf.y;
    out[65536 + base + sub]     = cf.x;
    out[65536 + base + sub + 4] = cf.y;
}

// ---------------------------------------------------------------------------
extern "C" void kernel_launch(void* const* d_in, const int* in_sizes, int n_in,
                              void* d_out, int out_size) {
    const float* x  = (const float*)d_in[0];   // (16, 2048) fp32
    const float* wt = (const float*)d_in[1];   // (2048, 4096) fp32
    float* out = (float*)d_out;                // 131072 fp32: [s | c]

    pack_kernel<<<1024, 256>>>(wt);
    scan_kernel<<<128, 256>>>(x, out);
}